// round 9
// baseline (speedup 1.0000x reference)
#include <cuda_runtime.h>
#include <cstdint>

// Problem shape (fixed by the dataset; derived values cross-checked from in_sizes)
#define NMAX 50048
#define EMAX 800000
#define DD   128

// ---------------- static device scratch (no allocations allowed) ----------------
__device__ int   g_mode;                  // 1 = edge_index is int64, 0 = int32
__device__ int   g_deg[NMAX + 1];
__device__ int   g_rowstart[NMAX + 1];
__device__ int   g_cursor[NMAX + 1];
__device__ int   g_csr[EMAX];
__device__ float g_z [(size_t)NMAX * DD];   // x + agg
__device__ float g_t1[(size_t)NMAX * DD];   // relu(z@W1+b1)
__device__ float g_t2[(size_t)NMAX * DD];   // t1@W2+b2 (pre-BN)
__device__ float g_sum[DD], g_sq[DD];
__device__ float g_scale[DD], g_shift[DD];

// ---------------- packed f32x2 helpers (sm_103a FFMA2 path) ----------------
__device__ __forceinline__ unsigned long long pack2(float lo, float hi) {
    unsigned long long r;
    asm("mov.b64 %0, {%1, %2};" : "=l"(r) : "f"(lo), "f"(hi));
    return r;
}
__device__ __forceinline__ unsigned long long splat2(float a) {
    unsigned long long r;
    asm("mov.b64 %0, {%1, %1};" : "=l"(r) : "f"(a));
    return r;
}
__device__ __forceinline__ void fma2(unsigned long long& acc,
                                     unsigned long long a, unsigned long long b) {
    asm("fma.rn.f32x2 %0, %1, %2, %0;" : "+l"(acc) : "l"(a), "l"(b));
}
__device__ __forceinline__ float2 unpack2(unsigned long long v) {
    float2 r;
    asm("mov.b64 {%0, %1}, %2;" : "=f"(r.x), "=f"(r.y) : "l"(v));
    return r;
}

// ---------------- init: zero degree array + detect edge_index dtype ----------------
// int64 [2,E] with values < 50000 (non-negative) => every odd int32 word is 0.
// For int32 data the odd words are random node ids; P(all 32 zero) ~ (2e-5)^32.
__global__ void init_kernel(const void* ei, int n) {
    int i = blockIdx.x * blockDim.x + threadIdx.x;
    if (i <= n) g_deg[i] = 0;
    if (blockIdx.x == 0 && threadIdx.x < 32) {
        const int* p = (const int*)ei;
        int v = p[2 * threadIdx.x + 1];
        unsigned b = __ballot_sync(0xffffffffu, v == 0);
        if (threadIdx.x == 0) g_mode = (b == 0xffffffffu) ? 1 : 0;
    }
}

__global__ void hist_kernel(const void* ei, int E) {
    int e = blockIdx.x * blockDim.x + threadIdx.x;
    if (e >= E) return;
    int d;
    if (g_mode) d = (int)((const long long*)ei)[E + e];
    else        d = ((const int*)ei)[E + e];
    atomicAdd(&g_deg[d], 1);
}

// single-block exclusive scan over g_deg -> g_rowstart (and g_cursor copy)
__global__ void scan_kernel(int n) {
    __shared__ int sh[1024];
    int tid = threadIdx.x;
    int chunk = (n + 1023) >> 10;
    int a = tid * chunk; if (a > n) a = n;
    int b = a + chunk;   if (b > n) b = n;
    int s = 0;
    for (int i = a; i < b; i++) s += g_deg[i];
    sh[tid] = s;
    __syncthreads();
    for (int off = 1; off < 1024; off <<= 1) {
        int v = (tid >= off) ? sh[tid - off] : 0;
        __syncthreads();
        sh[tid] += v;
        __syncthreads();
    }
    int run = sh[tid] - s;
    for (int i = a; i < b; i++) {
        g_rowstart[i] = run;
        g_cursor[i]   = run;
        run += g_deg[i];
    }
    if (tid == 1023) g_rowstart[n] = sh[1023];
}

__global__ void scatter_kernel(const void* ei, int E) {
    int e = blockIdx.x * blockDim.x + threadIdx.x;
    if (e >= E) return;
    int s, d;
    if (g_mode) {
        const long long* p = (const long long*)ei;
        s = (int)p[e]; d = (int)p[E + e];
    } else {
        const int* p = (const int*)ei;
        s = p[e]; d = p[E + e];
    }
    int pos = atomicAdd(&g_cursor[d], 1);
    g_csr[pos] = s;
}

// z[i] = x[i] + sum_{j in N(i)} x[j]   (warp per node, float4 per lane)
// 4-way unrolled edge loop: 4 independent 16B loads in flight per lane per
// iteration to cover the ~234-cycle L2-hit latency.
// Block 0 additionally zeroes the BN stat accumulators for this layer (stream
// order guarantees completion before gemm<true>'s atomics).
__global__ void agg_kernel(const float* __restrict__ x, int n) {
    if (blockIdx.x == 0 && threadIdx.x < DD) {
        g_sum[threadIdx.x] = 0.f;
        g_sq [threadIdx.x] = 0.f;
    }
    int gw   = (blockIdx.x * blockDim.x + threadIdx.x) >> 5;
    int lane = threadIdx.x & 31;
    if (gw >= n) return;
    const float4* __restrict__ X = (const float4*)x;
    float4 acc = X[(size_t)gw * 32 + lane];
    int e  = g_rowstart[gw];
    int e1 = g_rowstart[gw + 1];
    for (; e + 3 < e1; e += 4) {
        int s0 = g_csr[e], s1 = g_csr[e + 1], s2 = g_csr[e + 2], s3 = g_csr[e + 3];
        float4 v0 = X[(size_t)s0 * 32 + lane];
        float4 v1 = X[(size_t)s1 * 32 + lane];
        float4 v2 = X[(size_t)s2 * 32 + lane];
        float4 v3 = X[(size_t)s3 * 32 + lane];
        acc.x += v0.x; acc.y += v0.y; acc.z += v0.z; acc.w += v0.w;
        acc.x += v1.x; acc.y += v1.y; acc.z += v1.z; acc.w += v1.w;
        acc.x += v2.x; acc.y += v2.y; acc.z += v2.z; acc.w += v2.w;
        acc.x += v3.x; acc.y += v3.y; acc.z += v3.z; acc.w += v3.w;
    }
    for (; e < e1; e++) {
        int s0 = g_csr[e];
        float4 v0 = X[(size_t)s0 * 32 + lane];
        acc.x += v0.x; acc.y += v0.y; acc.z += v0.z; acc.w += v0.w;
    }
    ((float4*)g_z)[(size_t)gw * 32 + lane] = acc;
}

// C[M,128] = A[M,128] @ W[128,128] + bias,  f32x2 FMA path.
// Double-buffered smem (one barrier per K-tile). The 8x4 FFMA2 micro-tile is
// processed in two 4x4 halves so only 4 splatted A pairs are live at once,
// keeping peak registers ~119 < 128 (no spills at occ 2).
// STATS=false: A=g_z,  C=g_t1, epilogue = ReLU        (GEMM1)
// STATS=true : A=g_t1, C=g_t2, epilogue = raw + BN column stats (GEMM2)
template <bool STATS>
__global__ void __launch_bounds__(256, 2) gemm_kernel(
    const float* __restrict__ W, const float* __restrict__ bias, int M)
{
    const float* __restrict__ A = STATS ? g_t1 : g_z;
    float* __restrict__ C       = STATS ? g_t2 : g_t1;

    __shared__ float As[2][16][128];   // A tile, transposed [k][m]
    __shared__ float Bs[2][16][128];   // W tile [k][n]
    __shared__ float ssum[128], ssq[128];

    int t  = threadIdx.x;
    int tx = t & 15;       // N direction: cols tx*8 .. tx*8+7
    int ty = t >> 4;       // M direction: rows ty*8 .. ty*8+7
    int m0 = blockIdx.x * 128;

    unsigned long long acc[8][4];
    {
        float bv[8];
#pragma unroll
        for (int j = 0; j < 8; j++) bv[j] = bias[tx * 8 + j];
#pragma unroll
        for (int i = 0; i < 8; i++)
#pragma unroll
            for (int j = 0; j < 4; j++)
                acc[i][j] = pack2(bv[2 * j], bv[2 * j + 1]);
    }

    float4 pa[2], pb[2];
    auto loadA = [&](int k0) {
#pragma unroll
        for (int i = 0; i < 2; i++) {
            int f = i * 256 + t;
            int m = f >> 2, q = (f & 3) * 4;
            int row = m0 + m;
            if (row < M) pa[i] = *(const float4*)&A[(size_t)row * 128 + k0 + q];
            else         pa[i] = make_float4(0.f, 0.f, 0.f, 0.f);
        }
    };
    auto loadB = [&](int k0) {
#pragma unroll
        for (int i = 0; i < 2; i++) {
            int f = i * 256 + t;
            int k = f >> 5, n4 = (f & 31) * 4;
            pb[i] = *(const float4*)&W[(size_t)(k0 + k) * 128 + n4];
        }
    };
    auto storeTile = [&](int buf) {
#pragma unroll
        for (int i = 0; i < 2; i++) {
            int f = i * 256 + t;
            int m = f >> 2, q = (f & 3) * 4;
            As[buf][q + 0][m] = pa[i].x;
            As[buf][q + 1][m] = pa[i].y;
            As[buf][q + 2][m] = pa[i].z;
            As[buf][q + 3][m] = pa[i].w;
            int k = f >> 5, n4 = (f & 31) * 4;
            *(float4*)&Bs[buf][k][n4] = pb[i];
        }
    };

    loadA(0); loadB(0);
    storeTile(0);
    __syncthreads();

#pragma unroll
    for (int it = 0; it < 8; it++) {
        int cur = it & 1;
        if (it < 7) { loadA((it + 1) * 16); loadB((it + 1) * 16); }

#pragma unroll
        for (int kk = 0; kk < 16; kk++) {
            unsigned long long b2[4];
            const unsigned long long* br =
                (const unsigned long long*)&Bs[cur][kk][tx * 8];
#pragma unroll
            for (int j = 0; j < 4; j++) b2[j] = br[j];
            // two 4x4 halves: only 4 splatted A pairs live at a time
#pragma unroll
            for (int h = 0; h < 2; h++) {
                float4 av = *(const float4*)&As[cur][kk][ty * 8 + h * 4];
                unsigned long long a2[4];
                a2[0] = splat2(av.x); a2[1] = splat2(av.y);
                a2[2] = splat2(av.z); a2[3] = splat2(av.w);
#pragma unroll
                for (int i = 0; i < 4; i++)
#pragma unroll
                    for (int j = 0; j < 4; j++)
                        fma2(acc[h * 4 + i][j], a2[i], b2[j]);
            }
        }

        if (it < 7) {
            storeTile(cur ^ 1);      // writes the buffer nobody is reading
            __syncthreads();         // single barrier per tile
        }
    }

    // ---- epilogue ----
    if (STATS) {
        __syncthreads();   // re-use smem region safely after last tile reads
        if (t < 128) { ssum[t] = 0.f; ssq[t] = 0.f; }
        __syncthreads();
    }

    float ts[8], tq[8];
#pragma unroll
    for (int j = 0; j < 8; j++) { ts[j] = 0.f; tq[j] = 0.f; }

#pragma unroll
    for (int i = 0; i < 8; i++) {
        int row = m0 + ty * 8 + i;
        if (row < M) {
            float v[8];
#pragma unroll
            for (int j = 0; j < 4; j++) {
                float2 c = unpack2(acc[i][j]);
                v[2 * j] = c.x; v[2 * j + 1] = c.y;
            }
            if (!STATS) {
#pragma unroll
                for (int j = 0; j < 8; j++) v[j] = fmaxf(v[j], 0.f);
            } else {
#pragma unroll
                for (int j = 0; j < 8; j++) { ts[j] += v[j]; tq[j] += v[j] * v[j]; }
            }
            *(float4*)&C[(size_t)row * 128 + tx * 8]     = make_float4(v[0], v[1], v[2], v[3]);
            *(float4*)&C[(size_t)row * 128 + tx * 8 + 4] = make_float4(v[4], v[5], v[6], v[7]);
        }
    }

    if (STATS) {
#pragma unroll
        for (int j = 0; j < 8; j++) {
            atomicAdd(&ssum[tx * 8 + j], ts[j]);
            atomicAdd(&ssq [tx * 8 + j], tq[j]);
        }
        __syncthreads();
        if (t < 128) {
            atomicAdd(&g_sum[t], ssum[t]);
            atomicAdd(&g_sq [t], ssq [t]);
        }
    }
}

__global__ void bnfin_kernel(const float* __restrict__ gamma,
                             const float* __restrict__ beta, float invN) {
    int c = threadIdx.x;
    float mean = g_sum[c] * invN;
    float var  = fmaxf(g_sq[c] * invN - mean * mean, 0.f);
    float sc   = gamma[c] * rsqrtf(var + 1e-5f);
    g_scale[c] = sc;
    g_shift[c] = beta[c] - mean * sc;
}

// out = relu(t2 * scale + shift), float4-vectorized; out doubles as next layer input
__global__ void norm_kernel(float* __restrict__ outp, int n4) {
    int i = blockIdx.x * blockDim.x + threadIdx.x;
    if (i >= n4) return;
    int c4 = i & 31;
    float4 v = ((const float4*)g_t2)[i];
    float4 s = ((const float4*)g_scale)[c4];
    float4 h = ((const float4*)g_shift)[c4];
    v.x = fmaxf(fmaf(v.x, s.x, h.x), 0.f);
    v.y = fmaxf(fmaf(v.y, s.y, h.y), 0.f);
    v.z = fmaxf(fmaf(v.z, s.z, h.z), 0.f);
    v.w = fmaxf(fmaf(v.w, s.w, h.w), 0.f);
    ((float4*)outp)[i] = v;
}

// ------------------------------------------------------------------
extern "C" void kernel_launch(void* const* d_in, const int* in_sizes, int n_in,
                              void* d_out, int out_size) {
    (void)n_in; (void)out_size;
    const float* h     = (const float*)d_in[0];
    const void*  ei    = d_in[1];
    const float* W1    = (const float*)d_in[2];
    const float* b1    = (const float*)d_in[3];
    const float* W2    = (const float*)d_in[4];
    const float* b2    = (const float*)d_in[5];
    const float* gamma = (const float*)d_in[6];
    const float* beta  = (const float*)d_in[7];
    float* out = (float*)d_out;

    int N = in_sizes[0] / DD;          // 50000
    int E = in_sizes[1] / 2;           // 800000
    int L = in_sizes[2] / (DD * DD);   // 2

    // ---- CSR build (shared across layers) ----
    init_kernel<<<(N + 256) / 256, 256>>>(ei, N);
    hist_kernel<<<(E + 255) / 256, 256>>>(ei, E);
    scan_kernel<<<1, 1024>>>(N);
    scatter_kernel<<<(E + 255) / 256, 256>>>(ei, E);

    int gemm_blocks = (N + 127) / 128;
    int agg_blocks  = (N * 32 + 255) / 256;   // warp per node
    int n4          = N * 32;                 // float4 count per feature map
    int norm_blocks = (n4 + 255) / 256;

    for (int l = 0; l < L; l++) {
        const float* x = (l == 0) ? h : (out + (size_t)(l - 1) * N * DD);
        agg_kernel<<<agg_blocks, 256>>>(x, N);
        gemm_kernel<false><<<gemm_blocks, 256>>>(W1 + (size_t)l * DD * DD,
                                                 b1 + (size_t)l * DD, N);
        gemm_kernel<true><<<gemm_blocks, 256>>>(W2 + (size_t)l * DD * DD,
                                                b2 + (size_t)l * DD, N);
        bnfin_kernel<<<1, 128>>>(gamma + (size_t)l * DD, beta + (size_t)l * DD,
                                 1.0f / (float)N);
        norm_kernel<<<norm_blocks, 256>>>(out + (size_t)l * N * DD, n4);
    }
}